// round 1
// baseline (speedup 1.0000x reference)
#include <cuda_runtime.h>
#include <cstdint>
#include <cstdio>

#define BB 32
#define HH 1024
#define SS 2048
#define VV 32000
#define H3 3072
#define H2 2048

// ---------------- scratch (device globals; no allocations) ----------------
__device__ float g_rnn_in[BB * H2];
__device__ float g_A[H3 * BB];
__device__ float g_Bm[H3 * BB];
__device__ float g_h0[BB * HH];
__device__ float g_h1[BB * HH];
__device__ float g_q[BB * HH];
__device__ float g_scores[BB * SS];
__device__ float g_ctx_part[4 * BB * HH];
__device__ float g_cat[BB * H2];
__device__ float g_logits[(size_t)VV * BB];
__device__ float g_red[BB * 2];

// ---------------- build rnn_in = concat(emb[ids], last_context) -----------
__global__ void build_rnn_in_kernel(const int* __restrict__ ids,
                                    const float* __restrict__ emb,
                                    const float* __restrict__ lctx)
{
    int idx = blockIdx.x * 256 + threadIdx.x;   // B * 2048
    int b = idx >> 11;
    int k = idx & 2047;
    float v;
    if (k < HH) v = emb[(size_t)ids[b] * HH + k];
    else        v = lctx[(size_t)b * HH + (k - HH)];
    g_rnn_in[idx] = v;
}

// ---------------- generic GEMM: out[j][b] = bias[j] + sum_k X[b][k] W[j][k]
// lane = batch (B=32 exactly one warp wide), 8 warps x 8 rows = 64 rows/CTA,
// K-chunks of 64, smem-staged W (broadcast LDS.128) + padded X.
__global__ void __launch_bounds__(256)
gemm_xw_kernel(const float* __restrict__ X, int ldx,
               const float* __restrict__ Wm,         // [M][K] row-major
               const float* __restrict__ bias,       // [M] or nullptr
               float* __restrict__ out,
               int M, int K, int out_bt)             // out_bt: out[b][j] else out[j][b]
{
    __shared__ float Ws[64 * 64];
    __shared__ float Xs[32 * 68];                    // pad to 68 floats (16B-aligned, conflict-free)
    const int tid = threadIdx.x, warp = tid >> 5, lane = tid & 31;
    const int row0 = blockIdx.x * 64;
    float acc[8] = {0.f, 0.f, 0.f, 0.f, 0.f, 0.f, 0.f, 0.f};

    for (int k0 = 0; k0 < K; k0 += 64) {
        __syncthreads();
        // W chunk: 64 rows x 16 float4
        #pragma unroll
        for (int i = 0; i < 4; i++) {
            int e = tid + i * 256;
            int r = e >> 4, kk4 = e & 15;
            reinterpret_cast<float4*>(Ws)[r * 16 + kk4] =
                *(reinterpret_cast<const float4*>(Wm + (size_t)(row0 + r) * K + k0) + kk4);
        }
        // X chunk: 32 rows x 16 float4 (padded stride 17 float4)
        #pragma unroll
        for (int i = 0; i < 2; i++) {
            int e = tid + i * 256;
            int b = e >> 4, kk4 = e & 15;
            float4 v = *(reinterpret_cast<const float4*>(X + (size_t)b * ldx + k0) + kk4);
            *reinterpret_cast<float4*>(&Xs[b * 68 + kk4 * 4]) = v;
        }
        __syncthreads();
        #pragma unroll
        for (int kk = 0; kk < 16; kk++) {
            float4 c = *reinterpret_cast<const float4*>(&Xs[lane * 68 + kk * 4]);
            #pragma unroll
            for (int r = 0; r < 8; r++) {
                float4 w = *reinterpret_cast<const float4*>(&Ws[(warp * 8 + r) * 64 + kk * 4]);
                acc[r] = fmaf(w.x, c.x, fmaf(w.y, c.y, fmaf(w.z, c.z, fmaf(w.w, c.w, acc[r]))));
            }
        }
    }
    #pragma unroll
    for (int r = 0; r < 8; r++) {
        int row = row0 + warp * 8 + r;
        float v = acc[r] + (bias ? bias[row] : 0.f);
        if (out_bt) out[(size_t)lane * M + row] = v;
        else        out[(size_t)row * BB + lane] = v;
    }
}

// Same, but W stored reduction-major: W[k][j]  (used for q = h1 @ W_attn)
__global__ void __launch_bounds__(256)
gemm_xwT_kernel(const float* __restrict__ X, int ldx,
                const float* __restrict__ Wm,        // [K][M]
                float* __restrict__ out,
                int M, int K, int out_bt)
{
    __shared__ float Ws[64 * 64];
    __shared__ float Xs[32 * 68];
    const int tid = threadIdx.x, warp = tid >> 5, lane = tid & 31;
    const int row0 = blockIdx.x * 64;
    float acc[8] = {0.f, 0.f, 0.f, 0.f, 0.f, 0.f, 0.f, 0.f};

    for (int k0 = 0; k0 < K; k0 += 64) {
        __syncthreads();
        // W chunk transposed into Ws[row][kk]
        #pragma unroll
        for (int i = 0; i < 16; i++) {
            int e = tid + i * 256;            // 4096 scalars
            int r = e & 63, kk = e >> 6;
            Ws[r * 64 + kk] = Wm[(size_t)(k0 + kk) * M + row0 + r];
        }
        #pragma unroll
        for (int i = 0; i < 2; i++) {
            int e = tid + i * 256;
            int b = e >> 4, kk4 = e & 15;
            float4 v = *(reinterpret_cast<const float4*>(X + (size_t)b * ldx + k0) + kk4);
            *reinterpret_cast<float4*>(&Xs[b * 68 + kk4 * 4]) = v;
        }
        __syncthreads();
        #pragma unroll
        for (int kk = 0; kk < 16; kk++) {
            float4 c = *reinterpret_cast<const float4*>(&Xs[lane * 68 + kk * 4]);
            #pragma unroll
            for (int r = 0; r < 8; r++) {
                float4 w = *reinterpret_cast<const float4*>(&Ws[(warp * 8 + r) * 64 + kk * 4]);
                acc[r] = fmaf(w.x, c.x, fmaf(w.y, c.y, fmaf(w.z, c.z, fmaf(w.w, c.w, acc[r]))));
            }
        }
    }
    #pragma unroll
    for (int r = 0; r < 8; r++) {
        int row = row0 + warp * 8 + r;
        if (out_bt) out[(size_t)lane * M + row] = acc[r];
        else        out[(size_t)row * BB + lane] = acc[r];
    }
}

// ---------------- GRU gate fusion ----------------
__global__ void gru_gate_kernel(const float* __restrict__ A,   // [3H][B] : x-side gates
                                const float* __restrict__ Bm,  // [3H][B] : h-side gates
                                const float* __restrict__ hprev, // [B][H]
                                float* __restrict__ hnew,        // [B][H]
                                float* __restrict__ out_hidden)  // [B][H]
{
    int idx = blockIdx.x * 256 + threadIdx.x;   // B*H
    int b = idx & 31;
    int i = idx >> 5;
    float ir = A[(size_t)i * BB + b],              hr = Bm[(size_t)i * BB + b];
    float iz = A[(size_t)(HH + i) * BB + b],       hz = Bm[(size_t)(HH + i) * BB + b];
    float in_ = A[(size_t)(2 * HH + i) * BB + b],  hn = Bm[(size_t)(2 * HH + i) * BB + b];
    float r = 1.f / (1.f + expf(-(ir + hr)));
    float z = 1.f / (1.f + expf(-(iz + hz)));
    float n = tanhf(in_ + r * hn);
    float hp = hprev[(size_t)b * HH + i];
    float h = (1.f - z) * n + z * hp;
    hnew[(size_t)b * HH + i] = h;
    out_hidden[(size_t)b * HH + i] = h;
}

// ---------------- scores[b][s] = enc[b][s][:] . q[b][:] ----------------
__global__ void __launch_bounds__(256)
scores_kernel(const float* __restrict__ enc, const float* __restrict__ q)
{
    __shared__ float qs[HH];
    int b = blockIdx.y;
    int s = blockIdx.x * 8 + (threadIdx.x >> 5);
    int lane = threadIdx.x & 31;
    for (int i = threadIdx.x; i < HH; i += 256) qs[i] = q[(size_t)b * HH + i];
    __syncthreads();
    const float4* e = reinterpret_cast<const float4*>(enc + ((size_t)b * SS + s) * HH);
    const float4* qv4 = reinterpret_cast<const float4*>(qs);
    float acc = 0.f;
    #pragma unroll
    for (int i = 0; i < 8; i++) {
        float4 ev = e[lane + 32 * i];
        float4 qv = qv4[lane + 32 * i];
        acc = fmaf(ev.x, qv.x, fmaf(ev.y, qv.y, fmaf(ev.z, qv.z, fmaf(ev.w, qv.w, acc))));
    }
    #pragma unroll
    for (int o = 16; o; o >>= 1) acc += __shfl_xor_sync(0xffffffffu, acc, o);
    if (lane == 0) g_scores[(size_t)b * SS + s] = acc;
}

// ---------------- softmax over S per batch; write attn output ----------------
__global__ void softmax_s_kernel(float* __restrict__ attn_out)
{
    __shared__ float exps[SS];
    __shared__ float red[8];
    int b = blockIdx.x, tid = threadIdx.x, lane = tid & 31, warp = tid >> 5;
    const float* sc = g_scores + (size_t)b * SS;
    float m = -1e30f;
    for (int s = tid; s < SS; s += 256) m = fmaxf(m, sc[s]);
    #pragma unroll
    for (int o = 16; o; o >>= 1) m = fmaxf(m, __shfl_xor_sync(0xffffffffu, m, o));
    if (!lane) red[warp] = m;
    __syncthreads();
    float M0 = red[0];
    #pragma unroll
    for (int i = 1; i < 8; i++) M0 = fmaxf(M0, red[i]);
    __syncthreads();
    float sum = 0.f;
    for (int s = tid; s < SS; s += 256) {
        float e = expf(sc[s] - M0);
        exps[s] = e;
        sum += e;
    }
    #pragma unroll
    for (int o = 16; o; o >>= 1) sum += __shfl_xor_sync(0xffffffffu, sum, o);
    if (!lane) red[warp] = sum;
    __syncthreads();
    float tot = red[0];
    #pragma unroll
    for (int i = 1; i < 8; i++) tot += red[i];
    float inv = 1.f / tot;
    for (int s = tid; s < SS; s += 256) attn_out[(size_t)b * SS + s] = exps[s] * inv;
}

// ---------------- context partials: split S 4 ways ----------------
__global__ void __launch_bounds__(128)
context_part_kernel(const float* __restrict__ enc, const float* __restrict__ attn)
{
    __shared__ float as[512];
    int hc = blockIdx.x;   // 0..1  (512 h each)
    int b  = blockIdx.y;   // 0..31
    int sp = blockIdx.z;   // 0..3  (512 s each)
    int tid = threadIdx.x; // 128  (float4 each -> 512 h)
    for (int i = tid; i < 512; i += 128) as[i] = attn[(size_t)b * SS + sp * 512 + i];
    __syncthreads();
    const float4* e = reinterpret_cast<const float4*>(
        enc + ((size_t)b * SS + (size_t)sp * 512) * HH + hc * 512) + tid;
    float4 a = {0.f, 0.f, 0.f, 0.f};
    #pragma unroll 8
    for (int s = 0; s < 512; s++) {
        float w = as[s];
        float4 ev = e[(size_t)s * (HH / 4)];
        a.x = fmaf(w, ev.x, a.x);
        a.y = fmaf(w, ev.y, a.y);
        a.z = fmaf(w, ev.z, a.z);
        a.w = fmaf(w, ev.w, a.w);
    }
    reinterpret_cast<float4*>(g_ctx_part)[((size_t)(sp * BB + b) * HH + hc * 512) / 4 + tid] = a;
}

// ---------------- build cat = [h1, context]; emit context output ----------------
__global__ void finalize_cat_kernel(float* __restrict__ out_ctx)
{
    int idx = blockIdx.x * 256 + threadIdx.x;   // B * 2048
    int b = idx >> 11;
    int k = idx & 2047;
    float v;
    if (k < HH) {
        v = g_h1[(size_t)b * HH + k];
    } else {
        int h = k - HH;
        v = g_ctx_part[((size_t)0 * BB + b) * HH + h]
          + g_ctx_part[((size_t)1 * BB + b) * HH + h]
          + g_ctx_part[((size_t)2 * BB + b) * HH + h]
          + g_ctx_part[((size_t)3 * BB + b) * HH + h];
        out_ctx[(size_t)b * HH + h] = v;
    }
    g_cat[idx] = v;
}

// ---------------- vocab softmax: reduce then write ----------------
__global__ void vocab_reduce_kernel()
{
    __shared__ float red[8];
    int b = blockIdx.x, tid = threadIdx.x, lane = tid & 31, warp = tid >> 5;
    float m = -1e30f;
    for (int v = tid; v < VV; v += 256) m = fmaxf(m, g_logits[(size_t)v * BB + b]);
    #pragma unroll
    for (int o = 16; o; o >>= 1) m = fmaxf(m, __shfl_xor_sync(0xffffffffu, m, o));
    if (!lane) red[warp] = m;
    __syncthreads();
    float M0 = red[0];
    #pragma unroll
    for (int i = 1; i < 8; i++) M0 = fmaxf(M0, red[i]);
    __syncthreads();
    float s = 0.f;
    for (int v = tid; v < VV; v += 256) s += __expf(g_logits[(size_t)v * BB + b] - M0);
    #pragma unroll
    for (int o = 16; o; o >>= 1) s += __shfl_xor_sync(0xffffffffu, s, o);
    if (!lane) red[warp] = s;
    __syncthreads();
    if (tid == 0) {
        float t = 0.f;
        for (int i = 0; i < 8; i++) t += red[i];
        g_red[2 * b] = M0;
        g_red[2 * b + 1] = 1.f / t;
    }
}

__global__ void vocab_write_kernel(float* __restrict__ out)
{
    int idx = blockIdx.x * 256 + threadIdx.x;   // B * V, b-major
    int b = idx / VV;
    int v = idx - b * VV;
    out[idx] = __expf(g_logits[(size_t)v * BB + b] - g_red[2 * b]) * g_red[2 * b + 1];
}

// ---------------- launch ----------------
extern "C" void kernel_launch(void* const* d_in, const int* in_sizes, int n_in,
                              void* d_out, int out_size)
{
    const int*   ids  = (const int*)  d_in[0];
    const float* lctx = (const float*)d_in[1];
    const float* hid  = (const float*)d_in[2];
    const float* enc  = (const float*)d_in[3];
    const float* emb  = (const float*)d_in[4];
    const float* Wat  = (const float*)d_in[5];
    // d_in[6] = b_attn: per-batch-constant score shift -> softmax-invariant, skipped
    const float* Wih0 = (const float*)d_in[7];
    const float* Whh0 = (const float*)d_in[8];
    const float* bih0 = (const float*)d_in[9];
    const float* bhh0 = (const float*)d_in[10];
    const float* Wih1 = (const float*)d_in[11];
    const float* Whh1 = (const float*)d_in[12];
    const float* bih1 = (const float*)d_in[13];
    const float* bhh1 = (const float*)d_in[14];
    const float* Wout = (const float*)d_in[15];
    const float* bout = (const float*)d_in[16];

    float* out        = (float*)d_out;
    float* out_output = out;                               // [B][V]
    float* out_ctx    = out + (size_t)BB * VV;             // [1][B][H]
    float* out_hidden = out_ctx + (size_t)BB * HH;         // [2][B][H]
    float* out_attn   = out_hidden + (size_t)2 * BB * HH;  // [B][1][S]

    float *pRnn, *pA, *pB, *pH0, *pH1, *pQ, *pLog;
    cudaGetSymbolAddress((void**)&pRnn, g_rnn_in);
    cudaGetSymbolAddress((void**)&pA,   g_A);
    cudaGetSymbolAddress((void**)&pB,   g_Bm);
    cudaGetSymbolAddress((void**)&pH0,  g_h0);
    cudaGetSymbolAddress((void**)&pH1,  g_h1);
    cudaGetSymbolAddress((void**)&pQ,   g_q);
    cudaGetSymbolAddress((void**)&pLog, g_logits);

    // 1. rnn_in = concat(emb[ids], last_context)
    build_rnn_in_kernel<<<(BB * H2) / 256, 256>>>(ids, emb, lctx);
    // 2. GRU layer 0
    gemm_xw_kernel<<<H3 / 64, 256>>>(pRnn, H2, Wih0, bih0, pA, H3, H2, 0);
    gemm_xw_kernel<<<H3 / 64, 256>>>(hid,  HH, Whh0, bhh0, pB, H3, HH, 0);
    gru_gate_kernel<<<(BB * HH) / 256, 256>>>(pA, pB, hid, pH0, out_hidden);
    // 3. GRU layer 1
    gemm_xw_kernel<<<H3 / 64, 256>>>(pH0, HH, Wih1, bih1, pA, H3, HH, 0);
    gemm_xw_kernel<<<H3 / 64, 256>>>(hid + (size_t)BB * HH, HH, Whh1, bhh1, pB, H3, HH, 0);
    gru_gate_kernel<<<(BB * HH) / 256, 256>>>(pA, pB, hid + (size_t)BB * HH, pH1,
                                              out_hidden + (size_t)BB * HH);
    // 4. q[b] = h1[b] @ W_attn   (algebraic reordering of proj+einsum)
    gemm_xwT_kernel<<<HH / 64, 256>>>(pH1, HH, Wat, pQ, HH, HH, 1);
    // 5. scores + softmax + context
    scores_kernel<<<dim3(SS / 8, BB), 256>>>(enc, pQ);
    softmax_s_kernel<<<BB, 256>>>(out_attn);
    context_part_kernel<<<dim3(2, BB, 4), 128>>>(enc, out_attn);
    finalize_cat_kernel<<<(BB * H2) / 256, 256>>>(out_ctx);
    // 6. logits = cat @ W_out.T + b_out, softmax over V
    float* pCat;
    cudaGetSymbolAddress((void**)&pCat, g_cat);
    gemm_xw_kernel<<<VV / 64, 256>>>(pCat, H2, Wout, bout, pLog, VV, H2, 0);
    vocab_reduce_kernel<<<BB, 256>>>();
    vocab_write_kernel<<<(BB * VV) / 256, 256>>>(out_output);
}